// round 4
// baseline (speedup 1.0000x reference)
#include <cuda_runtime.h>
#include <math.h>

// Problem constants (fixed per metadata):
//   d_in[0] points     f32 [2,6144,3]
//   d_in[1] embeddings f32 [2,6144,32]
//   d_in[2] leaf_mask  i32 [2,6144]
//   d_in[3] W1 f32 [64,32], d_in[4] b1 [32], d_in[5] W2 [32,32], d_in[6] b2 [32]
//   out f32 [2,6144,32]
#define BB 2
#define NN 6144
#define DD 32
#define JS 32          // number of j-slices per batch (== warp size for k_final gather)
#define CAP 8          // max list entries per (point, slice); E[count] ~ 0.4
#define ITILE 1024     // compacted-i points per pairwise block (128 thr x 8)
#define FULL 0xffffffffu

// ---------------- device scratch (static, zero-init; every consumed cell is
// rewritten each launch or provably 0-stable -> deterministic replays) -------
__device__ float          g_norm[BB * NN];            // clamped |e_i|
__device__ float4         g_cpts[BB * NN];            // compacted leaf pts (x,y,z,pn)
__device__ unsigned short g_cidx[BB * NN];            // slot -> original index
__device__ int            g_slot[BB * NN];            // original -> slot (-1 if non-leaf)
__device__ int            g_nleaf[BB];                // leaf count per batch
__device__ unsigned char  g_nbcnt[BB * NN * JS];      // nb count per (slot, slice)
__device__ unsigned short g_list [BB * NN * JS * CAP];// nb j-indices (orig), j-ascending

// ---------------- K1: embedding norms ---------------------------------------
__global__ void k_norm(const float* __restrict__ emb) {
    int idx = blockIdx.x * blockDim.x + threadIdx.x;
    if (idx >= BB * NN) return;
    const float4* e = reinterpret_cast<const float4*>(emb) + (size_t)idx * 8;
    float s = 0.f;
#pragma unroll
    for (int k = 0; k < 8; k++) {
        float4 v = e[k];
        s += v.x * v.x; s += v.y * v.y; s += v.z * v.z; s += v.w * v.w;
    }
    g_norm[idx] = fmaxf(sqrtf(s), 1e-8f);
}

// ---------------- K2: leaf compaction (one block per batch) ------------------
__global__ __launch_bounds__(1024) void k_compact(const float* __restrict__ pts,
                                                  const int* __restrict__ leaf) {
    int b = blockIdx.x;
    int t = threadIdx.x;
    const int E = NN / 1024;  // 6 elements per thread
    __shared__ int wtot[32];
    int lm[E];
    int cnt = 0;
    int base = b * NN + t * E;
#pragma unroll
    for (int e = 0; e < E; e++) { lm[e] = (leaf[base + e] > 0) ? 1 : 0; cnt += lm[e]; }
    int lane = t & 31, w = t >> 5;
    int v = cnt;
#pragma unroll
    for (int o = 1; o < 32; o <<= 1) {
        int u = __shfl_up_sync(FULL, v, o);
        if (lane >= o) v += u;
    }
    if (lane == 31) wtot[w] = v;
    __syncthreads();
    if (w == 0) {
        int sv = wtot[lane];
#pragma unroll
        for (int o = 1; o < 32; o <<= 1) {
            int u = __shfl_up_sync(FULL, sv, o);
            if (lane >= o) sv += u;
        }
        wtot[lane] = sv;
    }
    __syncthreads();
    int pos = v - cnt + (w ? wtot[w - 1] : 0);  // exclusive prefix
#pragma unroll
    for (int e = 0; e < E; e++) {
        int i = t * E + e;
        if (lm[e]) {
            float x = pts[(size_t)(base + e) * 3 + 0];
            float y = pts[(size_t)(base + e) * 3 + 1];
            float z = pts[(size_t)(base + e) * 3 + 2];
            // pn = sum(p*p): squares rounded separately, summed left-to-right
            float pn = __fadd_rn(__fadd_rn(__fmul_rn(x, x), __fmul_rn(y, y)),
                                 __fmul_rn(z, z));
            g_cpts[b * NN + pos] = make_float4(x, y, z, pn);
            g_cidx[b * NN + pos] = (unsigned short)i;
            g_slot[base + e] = pos;
            pos++;
        } else {
            g_slot[base + e] = -1;
        }
    }
    if (t == 0) g_nleaf[b] = wtot[31];
}

// ---------------- K3: pairwise radius pass over compacted leaf points --------
// 128 threads x 8 register-blocked i's per thread = ITILE=1024 compacted i's.
__global__ __launch_bounds__(128) void k_pairs() {
    int b = blockIdx.z, s = blockIdx.y;
    int nl = g_nleaf[b];
    int cbase = blockIdx.x * ITILE;
    if (cbase >= nl) return;
    int L = (nl + JS - 1) / JS;     // <= 192
    int j0 = s * L;
    int j1 = min(j0 + L, nl);
    int len = j1 - j0;

    __shared__ float4         smp[192];
    __shared__ unsigned short smj[192];
    for (int k = threadIdx.x; k < len; k += 128) {
        smp[k] = g_cpts[b * NN + j0 + k];
        smj[k] = g_cidx[b * NN + j0 + k];
    }
    __syncthreads();

    const float R2 = (float)(0.03 * 0.03);

    float4 P[8];
    int    cn[8];
    size_t lbase[8];
#pragma unroll
    for (int k = 0; k < 8; k++) {
        int c = cbase + threadIdx.x + 128 * k;
        // inactive lanes get pn=+huge -> d2 always > R2, never pass
        P[k] = (c < nl) ? g_cpts[b * NN + c] : make_float4(0.f, 0.f, 0.f, 3.0e38f);
        cn[k] = 0;
        lbase[k] = (((size_t)(b * NN + c)) * JS + (size_t)s) * CAP;
    }

#pragma unroll 2
    for (int j = 0; j < len; j++) {
        float4 q = smp[j];
        bool pass[8];
        bool any = false;
#pragma unroll
        for (int k = 0; k < 8; k++) {
            // dot = fma chain; d2 = round((pni+pnj) - 2*dot)  [matches reference]
            float dot = fmaf(P[k].z, q.z, fmaf(P[k].y, q.y, __fmul_rn(P[k].x, q.x)));
            float d2  = fmaf(-2.f, dot, __fadd_rn(P[k].w, q.w));
            pass[k] = d2 < R2;
            any |= pass[k];
        }
        if (any) {
            unsigned short jj = smj[j];
#pragma unroll
            for (int k = 0; k < 8; k++) {
                if (pass[k]) {
                    if (cn[k] < CAP) g_list[lbase[k] + cn[k]] = jj;
                    cn[k]++;
                }
            }
        }
    }
#pragma unroll
    for (int k = 0; k < 8; k++) {
        int c = cbase + threadIdx.x + 128 * k;
        g_nbcnt[((size_t)(b * NN + c)) * JS + s] =
            (unsigned char)(cn[k] > 255 ? 255 : cn[k]);
    }
}

// ---------------- K4: sparse sims + MLP + output (one warp per point) --------
// Sim pass is lane=neighbor: 32 candidate pairs resolved per pipelined burst
// (independent broadcast-shuffles + FMA), no serial butterfly-reduce chains.
__global__ __launch_bounds__(256) void k_final(const float* __restrict__ emb,
                                               const float* __restrict__ W1,
                                               const float* __restrict__ b1,
                                               const float* __restrict__ W2,
                                               const float* __restrict__ b2,
                                               float* __restrict__ out) {
    __shared__ float sW1[64 * 32], sW2[32 * 32], sb1[32], sb2[32];
    __shared__ unsigned short smlist[8][JS * CAP];   // per-warp candidate j's
    int t = threadIdx.x;
    for (int k = t; k < 2048; k += 256) sW1[k] = W1[k];
    for (int k = t; k < 1024; k += 256) sW2[k] = W2[k];
    if (t < 32) { sb1[t] = b1[t]; sb2[t] = b2[t]; }
    __syncthreads();

    int wi   = t >> 5;                     // warp in block
    int w    = blockIdx.x * 8 + wi;        // global point id 0..B*N-1
    int lane = t & 31;                     // dim (phases B/C) or neighbor (phase A)
    int b    = w / NN;
    int bNN  = b * NN;

    float ei  = emb[(size_t)w * DD + lane];
    float val = ei;

    int slot = g_slot[w];
    if (g_nleaf[b] >= 10 && slot >= 0) {
        float ni  = g_norm[w];
        float thr = __fmul_rn(0.7f, ni);

        // --- gather candidates: lane = slice (JS == 32) -----------------
        const unsigned char*  cp = &g_nbcnt[((size_t)(bNN + slot)) * JS];
        const unsigned short* lp = &g_list [((size_t)(bNN + slot)) * JS * CAP];
        int cs = cp[lane];
        int ne = min(cs, CAP);
        // exclusive prefix of ne across lanes
        int off = ne;
#pragma unroll
        for (int o = 1; o < 32; o <<= 1) {
            int u = __shfl_up_sync(FULL, off, o);
            if (lane >= o) off += u;
        }
        int nc  = __shfl_sync(FULL, off, 31);  // total candidates
        off -= ne;
        int cnb = cs;                          // total in-radius count (incl overflow)
#pragma unroll
        for (int o = 16; o > 0; o >>= 1) cnb += __shfl_xor_sync(FULL, cnb, o);
        for (int e = 0; e < ne; e++) smlist[wi][off + e] = lp[lane * CAP + e];
        __syncwarp();

        // --- phase A: lane = candidate, 32 dots per burst ---------------
        float acc = 0.f;
        int   cns = 0;
        const float4* emb4 = reinterpret_cast<const float4*>(emb);
        for (int base = 0; base < nc; base += 32) {
            int  idx   = base + lane;
            bool valid = idx < nc;
            int  j     = valid ? (int)smlist[wi][idx] : 0;
            const float4* ej4 = emb4 + ((size_t)(bNN + j)) * 8;
            float d0 = 0.f, d1 = 0.f, d2 = 0.f, d3 = 0.f;
#pragma unroll
            for (int q = 0; q < 8; q++) {
                float4 v = ej4[q];
                d0 = fmaf(__shfl_sync(FULL, ei, 4 * q + 0), v.x, d0);
                d1 = fmaf(__shfl_sync(FULL, ei, 4 * q + 1), v.y, d1);
                d2 = fmaf(__shfl_sync(FULL, ei, 4 * q + 2), v.z, d2);
                d3 = fmaf(__shfl_sync(FULL, ei, 4 * q + 3), v.w, d3);
            }
            float dot = (d0 + d1) + (d2 + d3);
            float nj  = g_norm[bNN + j];
            bool pass = valid && (dot > __fmul_rn(thr, nj));
            unsigned mask = __ballot_sync(FULL, pass);
            cns += __popc(mask);
            // phase B: accumulate passing rows, lane = dim (L1-hot reloads)
            while (mask) {
                int l = __ffs(mask) - 1;
                mask &= mask - 1;
                int jj = __shfl_sync(FULL, j, l);
                acc += emb[((size_t)(bNN + jj)) * DD + lane];
            }
        }

        // --- phase C: MLP, lane = dim -----------------------------------
        if (cnb > 1 && cns > 0) {
            float mean = acc / (float)cns;
            float h = sb1[lane];
#pragma unroll
            for (int k = 0; k < 32; k++)
                h = fmaf(__shfl_sync(FULL, ei, k), sW1[k * DD + lane], h);
#pragma unroll
            for (int k = 0; k < 32; k++)
                h = fmaf(__shfl_sync(FULL, mean, k), sW1[(k + 32) * DD + lane], h);
            h = fmaxf(h, 0.f);
            float o = sb2[lane];
#pragma unroll
            for (int k = 0; k < 32; k++)
                o = fmaf(__shfl_sync(FULL, h, k), sW2[k * DD + lane], o);
            val = o;
        }
    }
    out[(size_t)w * DD + lane] = val;
}

// ---------------- launch -----------------------------------------------------
extern "C" void kernel_launch(void* const* d_in, const int* in_sizes, int n_in,
                              void* d_out, int out_size) {
    const float* points = (const float*)d_in[0];
    const float* emb    = (const float*)d_in[1];
    const int*   leaf   = (const int*)d_in[2];
    const float* W1     = (const float*)d_in[3];
    const float* b1     = (const float*)d_in[4];
    const float* W2     = (const float*)d_in[5];
    const float* b2     = (const float*)d_in[6];
    float*       out    = (float*)d_out;

    k_norm<<<(BB * NN + 255) / 256, 256>>>(emb);
    k_compact<<<BB, 1024>>>(points, leaf);
    dim3 g2((NN + ITILE - 1) / ITILE, JS, BB);
    k_pairs<<<g2, 128>>>();
    k_final<<<(BB * NN) / 8, 256>>>(emb, W1, b1, W2, b2, out);
}

// round 5
// speedup vs baseline: 1.4723x; 1.4723x over previous
#include <cuda_runtime.h>
#include <math.h>

// Problem constants (fixed per metadata):
//   d_in[0] points     f32 [2,6144,3]
//   d_in[1] embeddings f32 [2,6144,32]
//   d_in[2] leaf_mask  i32 [2,6144]
//   d_in[3] W1 f32 [64,32], d_in[4] b1 [32], d_in[5] W2 [32,32], d_in[6] b2 [32]
//   out f32 [2,6144,32]
#define BB 2
#define NN 6144
#define DD 32
#define JS 16          // number of j-slices per batch (R1-proven config)
#define CAP 16         // max list entries per (point, slice)
#define ITILE 512      // compacted-i points per pairwise block (128 thr x 4)
#define FULL 0xffffffffu

// ---------------- device scratch (static, zero-init; every consumed cell is
// rewritten each launch or provably 0-stable -> deterministic replays) -------
__device__ float          g_norm[BB * NN];            // clamped |e_i|
__device__ float4         g_cpts[BB * NN];            // compacted leaf pts (x,y,z,pn)
__device__ unsigned short g_cidx[BB * NN];            // slot -> original index
__device__ int            g_slot[BB * NN];            // original -> slot (-1 if non-leaf)
__device__ int            g_nleaf[BB];                // leaf count per batch
__device__ unsigned char  g_nbcnt[BB * NN * JS];      // nb count per (slot, slice)
__device__ unsigned short g_list [BB * NN * JS * CAP];// nb j-indices (orig), j-ascending

// ---------------- K1: embedding norms ---------------------------------------
__global__ void k_norm(const float* __restrict__ emb) {
    int idx = blockIdx.x * blockDim.x + threadIdx.x;
    if (idx >= BB * NN) return;
    const float4* e = reinterpret_cast<const float4*>(emb) + (size_t)idx * 8;
    float s = 0.f;
#pragma unroll
    for (int k = 0; k < 8; k++) {
        float4 v = e[k];
        s += v.x * v.x; s += v.y * v.y; s += v.z * v.z; s += v.w * v.w;
    }
    g_norm[idx] = fmaxf(sqrtf(s), 1e-8f);
}

// ---------------- K2: leaf compaction (one block per batch) ------------------
__global__ __launch_bounds__(1024) void k_compact(const float* __restrict__ pts,
                                                  const int* __restrict__ leaf) {
    int b = blockIdx.x;
    int t = threadIdx.x;
    const int E = NN / 1024;  // 6 elements per thread
    __shared__ int wtot[32];
    int lm[E];
    int cnt = 0;
    int base = b * NN + t * E;
#pragma unroll
    for (int e = 0; e < E; e++) { lm[e] = (leaf[base + e] > 0) ? 1 : 0; cnt += lm[e]; }
    int lane = t & 31, w = t >> 5;
    int v = cnt;
#pragma unroll
    for (int o = 1; o < 32; o <<= 1) {
        int u = __shfl_up_sync(FULL, v, o);
        if (lane >= o) v += u;
    }
    if (lane == 31) wtot[w] = v;
    __syncthreads();
    if (w == 0) {
        int sv = wtot[lane];
#pragma unroll
        for (int o = 1; o < 32; o <<= 1) {
            int u = __shfl_up_sync(FULL, sv, o);
            if (lane >= o) sv += u;
        }
        wtot[lane] = sv;
    }
    __syncthreads();
    int pos = v - cnt + (w ? wtot[w - 1] : 0);  // exclusive prefix
#pragma unroll
    for (int e = 0; e < E; e++) {
        int i = t * E + e;
        if (lm[e]) {
            float x = pts[(size_t)(base + e) * 3 + 0];
            float y = pts[(size_t)(base + e) * 3 + 1];
            float z = pts[(size_t)(base + e) * 3 + 2];
            // pn = sum(p*p): squares rounded separately, summed left-to-right
            float pn = __fadd_rn(__fadd_rn(__fmul_rn(x, x), __fmul_rn(y, y)),
                                 __fmul_rn(z, z));
            g_cpts[b * NN + pos] = make_float4(x, y, z, pn);
            g_cidx[b * NN + pos] = (unsigned short)i;
            g_slot[base + e] = pos;
            pos++;
        } else {
            g_slot[base + e] = -1;
        }
    }
    if (t == 0) g_nleaf[b] = wtot[31];
}

// ---------------- K3: pairwise radius pass (R1-proven config) ----------------
__global__ __launch_bounds__(128) void k_pairs() {
    int b = blockIdx.z, s = blockIdx.y;
    int nl = g_nleaf[b];
    int cbase = blockIdx.x * ITILE;
    if (cbase >= nl) return;
    int L = (nl + JS - 1) / JS;
    int j0 = s * L;
    int j1 = min(j0 + L, nl);
    int len = j1 - j0;  // <= 384

    __shared__ float4         smp[384];
    __shared__ unsigned short smj[384];
    for (int k = threadIdx.x; k < len; k += 128) {
        smp[k] = g_cpts[b * NN + j0 + k];
        smj[k] = g_cidx[b * NN + j0 + k];
    }
    __syncthreads();

    const float R2 = (float)(0.03 * 0.03);

    float4 P[4];
    int    cn[4];
    size_t lbase[4];
#pragma unroll
    for (int k = 0; k < 4; k++) {
        int c = cbase + threadIdx.x + 128 * k;
        // inactive lanes get pn=+huge -> d2 always > R2, never pass
        P[k] = (c < nl) ? g_cpts[b * NN + c] : make_float4(0.f, 0.f, 0.f, 3.0e38f);
        cn[k] = 0;
        lbase[k] = (((size_t)(b * NN + c)) * JS + (size_t)s) * CAP;
    }

#pragma unroll 4
    for (int j = 0; j < len; j++) {
        float4 q = smp[j];
        bool pass[4];
#pragma unroll
        for (int k = 0; k < 4; k++) {
            // dot = fma chain; d2 = round((pni+pnj) - 2*dot)  [matches reference]
            float dot = fmaf(P[k].z, q.z, fmaf(P[k].y, q.y, __fmul_rn(P[k].x, q.x)));
            float d2  = fmaf(-2.f, dot, __fadd_rn(P[k].w, q.w));
            pass[k] = d2 < R2;
        }
        if (pass[0] | pass[1] | pass[2] | pass[3]) {
            unsigned short jj = smj[j];
#pragma unroll
            for (int k = 0; k < 4; k++) {
                if (pass[k]) {
                    if (cn[k] < CAP) g_list[lbase[k] + cn[k]] = jj;
                    cn[k]++;
                }
            }
        }
    }
#pragma unroll
    for (int k = 0; k < 4; k++) {
        int c = cbase + threadIdx.x + 128 * k;
        g_nbcnt[((size_t)(b * NN + c)) * JS + s] =
            (unsigned char)(cn[k] > 255 ? 255 : cn[k]);
    }
}

// ---------------- K4: sparse sims + MLP + output (one warp per point) --------
// Phase A: lane = candidate; ei is broadcast via shared memory so invalid
// lanes are fully predicated off -> loads issued ONLY for real candidates.
__global__ __launch_bounds__(256) void k_final(const float* __restrict__ emb,
                                               const float* __restrict__ W1,
                                               const float* __restrict__ b1,
                                               const float* __restrict__ W2,
                                               const float* __restrict__ b2,
                                               float* __restrict__ out) {
    __shared__ float sW1[64 * 32], sW2[32 * 32], sb1[32], sb2[32];
    __shared__ float sei[8][32];                    // per-warp center embedding
    __shared__ unsigned short smlist[8][JS * CAP];  // per-warp candidate j's
    int t = threadIdx.x;
    for (int k = t; k < 2048; k += 256) sW1[k] = W1[k];
    for (int k = t; k < 1024; k += 256) sW2[k] = W2[k];
    if (t < 32) { sb1[t] = b1[t]; sb2[t] = b2[t]; }
    __syncthreads();

    int wi   = t >> 5;                     // warp in block
    int w    = blockIdx.x * 8 + wi;        // global point id 0..B*N-1
    int lane = t & 31;
    int b    = w / NN;
    int bNN  = b * NN;

    float ei  = emb[(size_t)w * DD + lane];
    float val = ei;

    int slot = g_slot[w];
    if (g_nleaf[b] >= 10 && slot >= 0) {
        sei[wi][lane] = ei;
        __syncwarp();
        float ni  = g_norm[w];
        float thr = __fmul_rn(0.7f, ni);

        // --- gather candidates: lanes 0..JS-1 own one slice each --------
        const unsigned char*  cp = &g_nbcnt[((size_t)(bNN + slot)) * JS];
        const unsigned short* lp = &g_list [((size_t)(bNN + slot)) * JS * CAP];
        int cs = (lane < JS) ? cp[lane] : 0;
        int ne = min(cs, CAP);
        int off = ne;
#pragma unroll
        for (int o = 1; o < 32; o <<= 1) {
            int u = __shfl_up_sync(FULL, off, o);
            if (lane >= o) off += u;
        }
        int nc  = __shfl_sync(FULL, off, 31);  // total candidates
        off -= ne;
        int cnb = cs;                          // total in-radius (incl overflow)
#pragma unroll
        for (int o = 16; o > 0; o >>= 1) cnb += __shfl_xor_sync(FULL, cnb, o);
        for (int e = 0; e < ne; e++) smlist[wi][off + e] = lp[lane * CAP + e];
        __syncwarp();

        // --- phase A: lane = candidate; predicated loads ----------------
        float acc = 0.f;
        int   cns = 0;
        const float4* emb4 = reinterpret_cast<const float4*>(emb);
        const float4* s4   = reinterpret_cast<const float4*>(sei[wi]);
        for (int base = 0; base < nc; base += 32) {
            int  idx   = base + lane;
            bool valid = idx < nc;
            int  j     = 0;
            bool pass  = false;
            if (valid) {
                j = (int)smlist[wi][idx];
                const float4* ej4 = emb4 + ((size_t)(bNN + j)) * 8;
                float d0 = 0.f, d1 = 0.f, d2 = 0.f, d3 = 0.f;
#pragma unroll
                for (int q = 0; q < 8; q++) {
                    float4 v = ej4[q];
                    float4 u = s4[q];            // LDS broadcast (conflict-free)
                    d0 = fmaf(u.x, v.x, d0);
                    d1 = fmaf(u.y, v.y, d1);
                    d2 = fmaf(u.z, v.z, d2);
                    d3 = fmaf(u.w, v.w, d3);
                }
                float dot = (d0 + d1) + (d2 + d3);
                float nj  = g_norm[bNN + j];
                pass = dot > __fmul_rn(thr, nj);
            }
            unsigned mask = __ballot_sync(FULL, pass);
            cns += __popc(mask);
            // phase B: accumulate passing rows, lane = dim (L1-hot)
            while (mask) {
                int l = __ffs(mask) - 1;
                mask &= mask - 1;
                int jj = __shfl_sync(FULL, j, l);
                acc += emb[((size_t)(bNN + jj)) * DD + lane];
            }
        }

        // --- phase C: MLP, lane = dim -----------------------------------
        if (cnb > 1 && cns > 0) {
            float mean = acc / (float)cns;
            float h = sb1[lane];
#pragma unroll
            for (int k = 0; k < 32; k++)
                h = fmaf(__shfl_sync(FULL, ei, k), sW1[k * DD + lane], h);
#pragma unroll
            for (int k = 0; k < 32; k++)
                h = fmaf(__shfl_sync(FULL, mean, k), sW1[(k + 32) * DD + lane], h);
            h = fmaxf(h, 0.f);
            float o = sb2[lane];
#pragma unroll
            for (int k = 0; k < 32; k++)
                o = fmaf(__shfl_sync(FULL, h, k), sW2[k * DD + lane], o);
            val = o;
        }
    }
    out[(size_t)w * DD + lane] = val;
}

// ---------------- launch -----------------------------------------------------
extern "C" void kernel_launch(void* const* d_in, const int* in_sizes, int n_in,
                              void* d_out, int out_size) {
    const float* points = (const float*)d_in[0];
    const float* emb    = (const float*)d_in[1];
    const int*   leaf   = (const int*)d_in[2];
    const float* W1     = (const float*)d_in[3];
    const float* b1     = (const float*)d_in[4];
    const float* W2     = (const float*)d_in[5];
    const float* b2     = (const float*)d_in[6];
    float*       out    = (float*)d_out;

    k_norm<<<(BB * NN + 255) / 256, 256>>>(emb);
    k_compact<<<BB, 1024>>>(points, leaf);
    dim3 g2((NN + ITILE - 1) / ITILE, JS, BB);
    k_pairs<<<g2, 128>>>();
    k_final<<<(BB * NN) / 8, 256>>>(emb, W1, b1, W2, b2, out);
}

// round 6
// speedup vs baseline: 1.5310x; 1.0398x over previous
#include <cuda_runtime.h>
#include <math.h>

// Problem constants (fixed per metadata):
//   d_in[0] points     f32 [2,6144,3]
//   d_in[1] embeddings f32 [2,6144,32]
//   d_in[2] leaf_mask  i32 [2,6144]
//   d_in[3] W1 f32 [64,32], d_in[4] b1 [32], d_in[5] W2 [32,32], d_in[6] b2 [32]
//   out f32 [2,6144,32]
#define BB 2
#define NN 6144
#define DD 32
#define JS 16          // number of j-slices per batch (proven config)
#define CAP 16         // max list entries per (point, slice)
#define ITILE 512      // compacted-i points per pairwise block (128 thr x 4)
#define FULL 0xffffffffu
#define NCHUNK 48      // 12288 / 256 compaction chunks
#define KF_BLOCKS 384  // persistent k_final blocks (8 warps each, 4 pts/warp)

// ---------------- device scratch (static; every consumed cell is rewritten
// each launch -> deterministic replays) --------------------------------------
__device__ float          g_norm[BB * NN];            // clamped |e_i|
__device__ float4         g_cpts[BB * NN];            // compacted leaf pts (x,y,z,pn)
__device__ unsigned short g_cidx[BB * NN];            // slot -> original index
__device__ int            g_slot[BB * NN];            // original -> slot (-1 if non-leaf)
__device__ int            g_nleaf[BB];                // leaf count per batch
__device__ int            g_ccnt[NCHUNK];             // per-chunk leaf counts
__device__ int            g_coff[NCHUNK];             // per-chunk base (batch-relative)
__device__ unsigned char  g_nbcnt[BB * NN * JS];      // nb count per (slot, slice)
__device__ unsigned short g_list [BB * NN * JS * CAP];// nb j-indices (orig), j-ascending

// ---------------- K1: embedding norms + per-chunk leaf counts ---------------
__global__ __launch_bounds__(256) void k_normcount(const float* __restrict__ emb,
                                                   const int* __restrict__ leaf) {
    int idx = blockIdx.x * 256 + threadIdx.x;   // 48 blocks cover 12288
    const float4* e = reinterpret_cast<const float4*>(emb) + (size_t)idx * 8;
    float s = 0.f;
#pragma unroll
    for (int k = 0; k < 8; k++) {
        float4 v = e[k];
        s += v.x * v.x; s += v.y * v.y; s += v.z * v.z; s += v.w * v.w;
    }
    g_norm[idx] = fmaxf(sqrtf(s), 1e-8f);

    int lf = (leaf[idx] > 0) ? 1 : 0;
    __shared__ int wsum[8];
    int v = lf;
#pragma unroll
    for (int o = 16; o > 0; o >>= 1) v += __shfl_xor_sync(FULL, v, o);
    int lane = threadIdx.x & 31, w = threadIdx.x >> 5;
    if (lane == 0) wsum[w] = v;
    __syncthreads();
    if (threadIdx.x == 0) {
        int tot = 0;
#pragma unroll
        for (int k = 0; k < 8; k++) tot += wsum[k];
        g_ccnt[blockIdx.x] = tot;
    }
}

// ---------------- K2a: tiny scan of chunk counts (per batch) -----------------
__global__ void k_scan() {
    int t = threadIdx.x;
    if (t < BB) {
        int base = t * (NCHUNK / BB), s = 0;
        for (int i = 0; i < NCHUNK / BB; i++) { g_coff[base + i] = s; s += g_ccnt[base + i]; }
        g_nleaf[t] = s;
    }
}

// ---------------- K2b: scatter compacted leaf points -------------------------
__global__ __launch_bounds__(256) void k_scatter(const float* __restrict__ pts,
                                                 const int* __restrict__ leaf) {
    int idx = blockIdx.x * 256 + threadIdx.x;
    int b   = idx / NN;
    int lf  = (leaf[idx] > 0) ? 1 : 0;
    // block-exclusive prefix of lf
    __shared__ int wtot[8];
    int lane = threadIdx.x & 31, w = threadIdx.x >> 5;
    int v = lf;
#pragma unroll
    for (int o = 1; o < 32; o <<= 1) {
        int u = __shfl_up_sync(FULL, v, o);
        if (lane >= o) v += u;
    }
    if (lane == 31) wtot[w] = v;
    __syncthreads();
    if (w == 0 && lane < 8) {
        int sv = wtot[lane];
#pragma unroll
        for (int o = 1; o < 8; o <<= 1) {
            int u = __shfl_up_sync(0xffu, sv, o);
            if (lane >= o) sv += u;
        }
        wtot[lane] = sv;
    }
    __syncthreads();
    int pre = v - lf + (w ? wtot[w - 1] : 0);
    if (lf) {
        int pos = g_coff[blockIdx.x] + pre;
        float x = pts[(size_t)idx * 3 + 0];
        float y = pts[(size_t)idx * 3 + 1];
        float z = pts[(size_t)idx * 3 + 2];
        // pn = sum(p*p): squares rounded separately, summed left-to-right
        float pn = __fadd_rn(__fadd_rn(__fmul_rn(x, x), __fmul_rn(y, y)),
                             __fmul_rn(z, z));
        g_cpts[b * NN + pos] = make_float4(x, y, z, pn);
        g_cidx[b * NN + pos] = (unsigned short)(idx - b * NN);
        g_slot[idx] = pos;
    } else {
        g_slot[idx] = -1;
    }
}

// ---------------- K3: pairwise radius pass (proven config, unchanged) --------
__global__ __launch_bounds__(128) void k_pairs() {
    int b = blockIdx.z, s = blockIdx.y;
    int nl = g_nleaf[b];
    int cbase = blockIdx.x * ITILE;
    if (cbase >= nl) return;
    int L = (nl + JS - 1) / JS;
    int j0 = s * L;
    int j1 = min(j0 + L, nl);
    int len = j1 - j0;  // <= 384

    __shared__ float4         smp[384];
    __shared__ unsigned short smj[384];
    for (int k = threadIdx.x; k < len; k += 128) {
        smp[k] = g_cpts[b * NN + j0 + k];
        smj[k] = g_cidx[b * NN + j0 + k];
    }
    __syncthreads();

    const float R2 = (float)(0.03 * 0.03);

    float4 P[4];
    int    cn[4];
    size_t lbase[4];
#pragma unroll
    for (int k = 0; k < 4; k++) {
        int c = cbase + threadIdx.x + 128 * k;
        // inactive lanes get pn=+huge -> d2 always > R2, never pass
        P[k] = (c < nl) ? g_cpts[b * NN + c] : make_float4(0.f, 0.f, 0.f, 3.0e38f);
        cn[k] = 0;
        lbase[k] = (((size_t)(b * NN + c)) * JS + (size_t)s) * CAP;
    }

#pragma unroll 4
    for (int j = 0; j < len; j++) {
        float4 q = smp[j];
        bool pass[4];
#pragma unroll
        for (int k = 0; k < 4; k++) {
            // dot = fma chain; d2 = round((pni+pnj) - 2*dot)  [matches reference]
            float dot = fmaf(P[k].z, q.z, fmaf(P[k].y, q.y, __fmul_rn(P[k].x, q.x)));
            float d2  = fmaf(-2.f, dot, __fadd_rn(P[k].w, q.w));
            pass[k] = d2 < R2;
        }
        if (pass[0] | pass[1] | pass[2] | pass[3]) {
            unsigned short jj = smj[j];
#pragma unroll
            for (int k = 0; k < 4; k++) {
                if (pass[k]) {
                    if (cn[k] < CAP) g_list[lbase[k] + cn[k]] = jj;
                    cn[k]++;
                }
            }
        }
    }
#pragma unroll
    for (int k = 0; k < 4; k++) {
        int c = cbase + threadIdx.x + 128 * k;
        g_nbcnt[((size_t)(b * NN + c)) * JS + s] =
            (unsigned char)(cn[k] > 255 ? 255 : cn[k]);
    }
}

// ---------------- K4: persistent sparse sims + MLP ---------------------------
// One warp per point, 4 points per warp. MLP uses transposed weights in smem
// (lane = output dim, contiguous k -> LDS.128) + smem x-broadcast: ~120 instr
// per layer-pair vs 288 with shuffle broadcast, and 4-way split accumulators.
__global__ __launch_bounds__(256) void k_final(const float* __restrict__ emb,
                                               const float* __restrict__ W1,
                                               const float* __restrict__ b1,
                                               const float* __restrict__ W2,
                                               const float* __restrict__ b2,
                                               float* __restrict__ out) {
    __shared__ float sW1t[32 * 68];                 // [d][k], row stride 68 floats
    __shared__ float sW2t[32 * 36];                 // [d][k], row stride 36 floats
    __shared__ float sb1[32], sb2[32];
    __shared__ float sxm[8][64];                    // per-warp [ei | mean]
    __shared__ float shx[8][32];                    // per-warp hidden
    __shared__ unsigned short smlist[8][JS * CAP];  // per-warp candidate j's
    int t = threadIdx.x;
    for (int k = t; k < 2048; k += 256) { int kk = k >> 5, d = k & 31; sW1t[d * 68 + kk] = W1[k]; }
    for (int k = t; k < 1024; k += 256) { int kk = k >> 5, d = k & 31; sW2t[d * 36 + kk] = W2[k]; }
    if (t < 32) { sb1[t] = b1[t]; sb2[t] = b2[t]; }
    __syncthreads();

    int wi   = t >> 5;
    int lane = t & 31;
    const float4* emb4 = reinterpret_cast<const float4*>(emb);

    for (int w = blockIdx.x * 8 + wi; w < BB * NN; w += KF_BLOCKS * 8) {
        int b   = w / NN;
        int bNN = b * NN;

        float ei  = emb[(size_t)w * DD + lane];
        float val = ei;

        int slot = g_slot[w];
        if (g_nleaf[b] >= 10 && slot >= 0) {
            sxm[wi][lane] = ei;
            __syncwarp();
            float ni  = g_norm[w];
            float thr = __fmul_rn(0.7f, ni);

            // --- gather candidates: lanes 0..JS-1 own one slice each ----
            const unsigned char*  cp = &g_nbcnt[((size_t)(bNN + slot)) * JS];
            const unsigned short* lp = &g_list [((size_t)(bNN + slot)) * JS * CAP];
            int cs = (lane < JS) ? cp[lane] : 0;
            int ne = min(cs, CAP);
            int off = ne;
#pragma unroll
            for (int o = 1; o < 32; o <<= 1) {
                int u = __shfl_up_sync(FULL, off, o);
                if (lane >= o) off += u;
            }
            int nc  = __shfl_sync(FULL, off, 31);  // total candidates
            off -= ne;
            int cnb = cs;                          // total in-radius (incl overflow)
#pragma unroll
            for (int o = 16; o > 0; o >>= 1) cnb += __shfl_xor_sync(FULL, cnb, o);
            for (int e = 0; e < ne; e++) smlist[wi][off + e] = lp[lane * CAP + e];
            __syncwarp();

            // --- phase A: lane = candidate; predicated loads ------------
            float acc = 0.f;
            int   cns = 0;
            const float4* s4 = reinterpret_cast<const float4*>(sxm[wi]);
            for (int base = 0; base < nc; base += 32) {
                int  idx   = base + lane;
                bool valid = idx < nc;
                int  j     = 0;
                bool pass  = false;
                if (valid) {
                    j = (int)smlist[wi][idx];
                    const float4* ej4 = emb4 + ((size_t)(bNN + j)) * 8;
                    float d0 = 0.f, d1 = 0.f, d2 = 0.f, d3 = 0.f;
#pragma unroll
                    for (int q = 0; q < 8; q++) {
                        float4 v = ej4[q];
                        float4 u = s4[q];            // LDS broadcast
                        d0 = fmaf(u.x, v.x, d0);
                        d1 = fmaf(u.y, v.y, d1);
                        d2 = fmaf(u.z, v.z, d2);
                        d3 = fmaf(u.w, v.w, d3);
                    }
                    float dot = (d0 + d1) + (d2 + d3);
                    float nj  = g_norm[bNN + j];
                    pass = dot > __fmul_rn(thr, nj);
                }
                unsigned mask = __ballot_sync(FULL, pass);
                cns += __popc(mask);
                // phase B: accumulate passing rows, lane = dim (L1-hot)
                while (mask) {
                    int l = __ffs(mask) - 1;
                    mask &= mask - 1;
                    int jj = __shfl_sync(FULL, j, l);
                    acc += emb[((size_t)(bNN + jj)) * DD + lane];
                }
            }

            // --- phase C: MLP, lane = output dim ------------------------
            if (cnb > 1 && cns > 0) {
                float mean = acc / (float)cns;
                sxm[wi][32 + lane] = mean;
                __syncwarp();
                const float4* x4 = reinterpret_cast<const float4*>(sxm[wi]);
                float h0 = 0.f, h1 = 0.f, h2 = 0.f, h3 = 0.f;
#pragma unroll
                for (int q = 0; q < 16; q++) {
                    float4 xv = x4[q];
                    float4 wv = *reinterpret_cast<const float4*>(&sW1t[lane * 68 + 4 * q]);
                    h0 = fmaf(xv.x, wv.x, h0);
                    h1 = fmaf(xv.y, wv.y, h1);
                    h2 = fmaf(xv.z, wv.z, h2);
                    h3 = fmaf(xv.w, wv.w, h3);
                }
                float h = fmaxf(((h0 + h1) + (h2 + h3)) + sb1[lane], 0.f);
                shx[wi][lane] = h;
                __syncwarp();
                const float4* hx4 = reinterpret_cast<const float4*>(shx[wi]);
                float o0 = 0.f, o1 = 0.f, o2 = 0.f, o3 = 0.f;
#pragma unroll
                for (int q = 0; q < 8; q++) {
                    float4 xv = hx4[q];
                    float4 wv = *reinterpret_cast<const float4*>(&sW2t[lane * 36 + 4 * q]);
                    o0 = fmaf(xv.x, wv.x, o0);
                    o1 = fmaf(xv.y, wv.y, o1);
                    o2 = fmaf(xv.z, wv.z, o2);
                    o3 = fmaf(xv.w, wv.w, o3);
                }
                val = ((o0 + o1) + (o2 + o3)) + sb2[lane];
            }
        }
        out[(size_t)w * DD + lane] = val;
    }
}

// ---------------- launch -----------------------------------------------------
extern "C" void kernel_launch(void* const* d_in, const int* in_sizes, int n_in,
                              void* d_out, int out_size) {
    const float* points = (const float*)d_in[0];
    const float* emb    = (const float*)d_in[1];
    const int*   leaf   = (const int*)d_in[2];
    const float* W1     = (const float*)d_in[3];
    const float* b1     = (const float*)d_in[4];
    const float* W2     = (const float*)d_in[5];
    const float* b2     = (const float*)d_in[6];
    float*       out    = (float*)d_out;

    k_normcount<<<NCHUNK, 256>>>(emb, leaf);
    k_scan<<<1, 32>>>();
    k_scatter<<<NCHUNK, 256>>>(points, leaf);
    dim3 g2((NN + ITILE - 1) / ITILE, JS, BB);
    k_pairs<<<g2, 128>>>();
    k_final<<<KF_BLOCKS, 256>>>(emb, W1, b1, W2, b2, out);
}

// round 7
// speedup vs baseline: 1.9438x; 1.2697x over previous
#include <cuda_runtime.h>
#include <math.h>

// Problem constants (fixed per metadata):
//   d_in[0] points     f32 [2,6144,3]
//   d_in[1] embeddings f32 [2,6144,32]
//   d_in[2] leaf_mask  i32 [2,6144]
//   d_in[3] W1 f32 [64,32], d_in[4] b1 [32], d_in[5] W2 [32,32], d_in[6] b2 [32]
//   out f32 [2,6144,32]
#define BB 2
#define NN 6144
#define DD 32
#define JS 16          // number of j-slices per batch (proven config)
#define CAP 16         // max list entries per (point, slice)
#define ITILE 256      // compacted-i points per pairwise block (128 thr x 2)
#define FULL 0xffffffffu
#define NCHUNK 48      // 12288 / 256 compaction chunks
#define KF_BLOCKS 384  // persistent k_final blocks (8 warps each)

// ---------------- device scratch (static; every consumed cell is rewritten
// each launch -> deterministic replays) --------------------------------------
__device__ float          g_norm[BB * NN];            // clamped |e_i|
__device__ float4         g_cpts[BB * NN];            // compacted leaf pts (x,y,z,pn)
__device__ unsigned short g_cidx[BB * NN];            // slot -> original index
__device__ int            g_slot[BB * NN];            // original -> slot (-1 if non-leaf)
__device__ int            g_nleaf[BB];                // leaf count per batch
__device__ int            g_ccnt[NCHUNK];             // per-chunk leaf counts
__device__ int            g_coff[NCHUNK];             // per-chunk base (batch-relative)
__device__ unsigned char  g_nbcnt[BB * NN * JS];      // nb count per (slot, slice)
__device__ unsigned short g_list [BB * NN * JS * CAP];// nb j-indices (orig), j-ascending

// ---------------- K1: embedding norms + per-chunk leaf counts ---------------
__global__ __launch_bounds__(256) void k_normcount(const float* __restrict__ emb,
                                                   const int* __restrict__ leaf) {
    int idx = blockIdx.x * 256 + threadIdx.x;   // 48 blocks cover 12288
    const float4* e = reinterpret_cast<const float4*>(emb) + (size_t)idx * 8;
    float s = 0.f;
#pragma unroll
    for (int k = 0; k < 8; k++) {
        float4 v = e[k];
        s += v.x * v.x; s += v.y * v.y; s += v.z * v.z; s += v.w * v.w;
    }
    g_norm[idx] = fmaxf(sqrtf(s), 1e-8f);

    int lf = (leaf[idx] > 0) ? 1 : 0;
    __shared__ int wsum[8];
    int v = lf;
#pragma unroll
    for (int o = 16; o > 0; o >>= 1) v += __shfl_xor_sync(FULL, v, o);
    int lane = threadIdx.x & 31, w = threadIdx.x >> 5;
    if (lane == 0) wsum[w] = v;
    __syncthreads();
    if (threadIdx.x == 0) {
        int tot = 0;
#pragma unroll
        for (int k = 0; k < 8; k++) tot += wsum[k];
        g_ccnt[blockIdx.x] = tot;
    }
}

// ---------------- K2a: tiny scan of chunk counts (per batch) -----------------
__global__ void k_scan() {
    int t = threadIdx.x;
    if (t < BB) {
        int base = t * (NCHUNK / BB), s = 0;
        for (int i = 0; i < NCHUNK / BB; i++) { g_coff[base + i] = s; s += g_ccnt[base + i]; }
        g_nleaf[t] = s;
    }
}

// ---------------- K2b: scatter compacted leaf points -------------------------
__global__ __launch_bounds__(256) void k_scatter(const float* __restrict__ pts,
                                                 const int* __restrict__ leaf) {
    int idx = blockIdx.x * 256 + threadIdx.x;
    int b   = idx / NN;
    int lf  = (leaf[idx] > 0) ? 1 : 0;
    // block-exclusive prefix of lf
    __shared__ int wtot[8];
    int lane = threadIdx.x & 31, w = threadIdx.x >> 5;
    int v = lf;
#pragma unroll
    for (int o = 1; o < 32; o <<= 1) {
        int u = __shfl_up_sync(FULL, v, o);
        if (lane >= o) v += u;
    }
    if (lane == 31) wtot[w] = v;
    __syncthreads();
    if (w == 0 && lane < 8) {
        int sv = wtot[lane];
#pragma unroll
        for (int o = 1; o < 8; o <<= 1) {
            int u = __shfl_up_sync(0xffu, sv, o);
            if (lane >= o) sv += u;
        }
        wtot[lane] = sv;
    }
    __syncthreads();
    int pre = v - lf + (w ? wtot[w - 1] : 0);
    if (lf) {
        int pos = g_coff[blockIdx.x] + pre;
        float x = pts[(size_t)idx * 3 + 0];
        float y = pts[(size_t)idx * 3 + 1];
        float z = pts[(size_t)idx * 3 + 2];
        // pn = sum(p*p): squares rounded separately, summed left-to-right
        float pn = __fadd_rn(__fadd_rn(__fmul_rn(x, x), __fmul_rn(y, y)),
                             __fmul_rn(z, z));
        g_cpts[b * NN + pos] = make_float4(x, y, z, pn);
        g_cidx[b * NN + pos] = (unsigned short)(idx - b * NN);
        g_slot[idx] = pos;
    } else {
        g_slot[idx] = -1;
    }
}

// ---------------- K3: pairwise radius pass -----------------------------------
// ITILE=256: 2 register-blocked i's per thread, 2x the active blocks vs R5
// (occupancy was the binding constraint: occ 8.8%, issue 25%). smp[j+1] is
// software-prefetched so the LDS.128 is off the dependent-compare path.
__global__ __launch_bounds__(128) void k_pairs() {
    int b = blockIdx.z, s = blockIdx.y;
    int nl = g_nleaf[b];
    int cbase = blockIdx.x * ITILE;
    if (cbase >= nl) return;
    int L = (nl + JS - 1) / JS;
    int j0 = s * L;
    int j1 = min(j0 + L, nl);
    int len = j1 - j0;  // <= 384

    __shared__ float4         smp[384];
    __shared__ unsigned short smj[384];
    for (int k = threadIdx.x; k < len; k += 128) {
        smp[k] = g_cpts[b * NN + j0 + k];
        smj[k] = g_cidx[b * NN + j0 + k];
    }
    __syncthreads();

    const float R2 = (float)(0.03 * 0.03);

    float4 P[2];
    int    cn[2];
    size_t lbase[2];
#pragma unroll
    for (int k = 0; k < 2; k++) {
        int c = cbase + threadIdx.x + 128 * k;
        // inactive lanes get pn=+huge -> d2 always > R2, never pass
        P[k] = (c < nl) ? g_cpts[b * NN + c] : make_float4(0.f, 0.f, 0.f, 3.0e38f);
        cn[k] = 0;
        lbase[k] = (((size_t)(b * NN + c)) * JS + (size_t)s) * CAP;
    }

    float4 q = smp[0];
#pragma unroll 4
    for (int j = 0; j < len; j++) {
        float4 qn = smp[(j + 1 < len) ? j + 1 : j];   // prefetch next
        bool pass[2];
#pragma unroll
        for (int k = 0; k < 2; k++) {
            // dot = fma chain; d2 = round((pni+pnj) - 2*dot)  [matches reference]
            float dot = fmaf(P[k].z, q.z, fmaf(P[k].y, q.y, __fmul_rn(P[k].x, q.x)));
            float d2  = fmaf(-2.f, dot, __fadd_rn(P[k].w, q.w));
            pass[k] = d2 < R2;
        }
        if (pass[0] | pass[1]) {
            unsigned short jj = smj[j];
#pragma unroll
            for (int k = 0; k < 2; k++) {
                if (pass[k]) {
                    if (cn[k] < CAP) g_list[lbase[k] + cn[k]] = jj;
                    cn[k]++;
                }
            }
        }
        q = qn;
    }
#pragma unroll
    for (int k = 0; k < 2; k++) {
        int c = cbase + threadIdx.x + 128 * k;
        g_nbcnt[((size_t)(b * NN + c)) * JS + s] =
            (unsigned char)(cn[k] > 255 ? 255 : cn[k]);
    }
}

// ---------------- K4: persistent sparse sims + MLP ---------------------------
// One warp per point, persistent. MLP uses transposed weights in smem
// (lane = output dim, contiguous k -> LDS.128) + smem x-broadcast.
__global__ __launch_bounds__(256) void k_final(const float* __restrict__ emb,
                                               const float* __restrict__ W1,
                                               const float* __restrict__ b1,
                                               const float* __restrict__ W2,
                                               const float* __restrict__ b2,
                                               float* __restrict__ out) {
    __shared__ float sW1t[32 * 68];                 // [d][k], row stride 68 floats
    __shared__ float sW2t[32 * 36];                 // [d][k], row stride 36 floats
    __shared__ float sb1[32], sb2[32];
    __shared__ float sxm[8][64];                    // per-warp [ei | mean]
    __shared__ float shx[8][32];                    // per-warp hidden
    __shared__ unsigned short smlist[8][JS * CAP];  // per-warp candidate j's
    int t = threadIdx.x;
    for (int k = t; k < 2048; k += 256) { int kk = k >> 5, d = k & 31; sW1t[d * 68 + kk] = W1[k]; }
    for (int k = t; k < 1024; k += 256) { int kk = k >> 5, d = k & 31; sW2t[d * 36 + kk] = W2[k]; }
    if (t < 32) { sb1[t] = b1[t]; sb2[t] = b2[t]; }
    __syncthreads();

    int wi   = t >> 5;
    int lane = t & 31;
    const float4* emb4 = reinterpret_cast<const float4*>(emb);

    for (int w = blockIdx.x * 8 + wi; w < BB * NN; w += KF_BLOCKS * 8) {
        int b   = w / NN;
        int bNN = b * NN;

        float ei  = emb[(size_t)w * DD + lane];
        float val = ei;

        int slot = g_slot[w];
        if (g_nleaf[b] >= 10 && slot >= 0) {
            sxm[wi][lane] = ei;
            __syncwarp();
            float ni  = g_norm[w];
            float thr = __fmul_rn(0.7f, ni);

            // --- gather candidates: lanes 0..JS-1 own one slice each ----
            const unsigned char*  cp = &g_nbcnt[((size_t)(bNN + slot)) * JS];
            const unsigned short* lp = &g_list [((size_t)(bNN + slot)) * JS * CAP];
            int cs = (lane < JS) ? cp[lane] : 0;
            int ne = min(cs, CAP);
            int off = ne;
#pragma unroll
            for (int o = 1; o < 32; o <<= 1) {
                int u = __shfl_up_sync(FULL, off, o);
                if (lane >= o) off += u;
            }
            int nc  = __shfl_sync(FULL, off, 31);  // total candidates
            off -= ne;
            int cnb = cs;                          // total in-radius (incl overflow)
#pragma unroll
            for (int o = 16; o > 0; o >>= 1) cnb += __shfl_xor_sync(FULL, cnb, o);
            for (int e = 0; e < ne; e++) smlist[wi][off + e] = lp[lane * CAP + e];
            __syncwarp();

            // --- phase A: lane = candidate; predicated loads ------------
            float acc = 0.f;
            int   cns = 0;
            const float4* s4 = reinterpret_cast<const float4*>(sxm[wi]);
            for (int base = 0; base < nc; base += 32) {
                int  idx   = base + lane;
                bool valid = idx < nc;
                int  j     = 0;
                bool pass  = false;
                if (valid) {
                    j = (int)smlist[wi][idx];
                    const float4* ej4 = emb4 + ((size_t)(bNN + j)) * 8;
                    float d0 = 0.f, d1 = 0.f, d2 = 0.f, d3 = 0.f;
#pragma unroll
                    for (int q = 0; q < 8; q++) {
                        float4 v = ej4[q];
                        float4 u = s4[q];            // LDS broadcast
                        d0 = fmaf(u.x, v.x, d0);
                        d1 = fmaf(u.y, v.y, d1);
                        d2 = fmaf(u.z, v.z, d2);
                        d3 = fmaf(u.w, v.w, d3);
                    }
                    float dot = (d0 + d1) + (d2 + d3);
                    float nj  = g_norm[bNN + j];
                    pass = dot > __fmul_rn(thr, nj);
                }
                unsigned mask = __ballot_sync(FULL, pass);
                cns += __popc(mask);
                // phase B: accumulate passing rows, lane = dim (L1-hot)
                while (mask) {
                    int l = __ffs(mask) - 1;
                    mask &= mask - 1;
                    int jj = __shfl_sync(FULL, j, l);
                    acc += emb[((size_t)(bNN + jj)) * DD + lane];
                }
            }

            // --- phase C: MLP, lane = output dim ------------------------
            if (cnb > 1 && cns > 0) {
                float mean = acc / (float)cns;
                sxm[wi][32 + lane] = mean;
                __syncwarp();
                const float4* x4 = reinterpret_cast<const float4*>(sxm[wi]);
                float h0 = 0.f, h1 = 0.f, h2 = 0.f, h3 = 0.f;
#pragma unroll
                for (int q = 0; q < 16; q++) {
                    float4 xv = x4[q];
                    float4 wv = *reinterpret_cast<const float4*>(&sW1t[lane * 68 + 4 * q]);
                    h0 = fmaf(xv.x, wv.x, h0);
                    h1 = fmaf(xv.y, wv.y, h1);
                    h2 = fmaf(xv.z, wv.z, h2);
                    h3 = fmaf(xv.w, wv.w, h3);
                }
                float h = fmaxf(((h0 + h1) + (h2 + h3)) + sb1[lane], 0.f);
                shx[wi][lane] = h;
                __syncwarp();
                const float4* hx4 = reinterpret_cast<const float4*>(shx[wi]);
                float o0 = 0.f, o1 = 0.f, o2 = 0.f, o3 = 0.f;
#pragma unroll
                for (int q = 0; q < 8; q++) {
                    float4 xv = hx4[q];
                    float4 wv = *reinterpret_cast<const float4*>(&sW2t[lane * 36 + 4 * q]);
                    o0 = fmaf(xv.x, wv.x, o0);
                    o1 = fmaf(xv.y, wv.y, o1);
                    o2 = fmaf(xv.z, wv.z, o2);
                    o3 = fmaf(xv.w, wv.w, o3);
                }
                val = ((o0 + o1) + (o2 + o3)) + sb2[lane];
            }
        }
        out[(size_t)w * DD + lane] = val;
    }
}

// ---------------- launch -----------------------------------------------------
extern "C" void kernel_launch(void* const* d_in, const int* in_sizes, int n_in,
                              void* d_out, int out_size) {
    const float* points = (const float*)d_in[0];
    const float* emb    = (const float*)d_in[1];
    const int*   leaf   = (const int*)d_in[2];
    const float* W1     = (const float*)d_in[3];
    const float* b1     = (const float*)d_in[4];
    const float* W2     = (const float*)d_in[5];
    const float* b2     = (const float*)d_in[6];
    float*       out    = (float*)d_out;

    k_normcount<<<NCHUNK, 256>>>(emb, leaf);
    k_scan<<<1, 32>>>();
    k_scatter<<<NCHUNK, 256>>>(points, leaf);
    dim3 g2((NN + ITILE - 1) / ITILE, JS, BB);
    k_pairs<<<g2, 128>>>();
    k_final<<<KF_BLOCKS, 256>>>(emb, W1, b1, W2, b2, out);
}